// round 1
// baseline (speedup 1.0000x reference)
#include <cuda_runtime.h>
#include <math.h>

// ---------------- problem constants ----------------
#define BB   4
#define SS   1024
#define DIN  768
#define DD   224
#define HH   8
#define DKK  28
#define FFD  600
#define VV   8000
#define LL   8
#define MM   (BB*SS)        // 4096 rows
#define SD   (SS*DD)        // 229376 per-batch LN size
#define QKVN (3*HH*DKK)     // 672

// ---------------- device scratch (static, no allocs) ----------------
__device__ float  g_h   [MM*DD];
__device__ float  g_a   [MM*DD];
__device__ float  g_ctx [MM*DD];
__device__ float  g_qkv [MM*QKVN];
__device__ float  g_f1  [MM*FFD];
__device__ float  g_f2  [MM*FFD];
__device__ float  g_wqkv[DD*QKVN];
__device__ float  g_bqkv[QKVN];
__device__ float2 g_part[BB*64];
__device__ float2 g_stats[BB];

// ---------------- generic tiled SGEMM ----------------
// C[M,N] = A[M,K] @ B[K,N] (+bias[n]) (+res[m,n]) (optional relu)
template<bool RELU>
__global__ void sgemm_kernel(const float* __restrict__ A, const float* __restrict__ B,
                             const float* __restrict__ bias, const float* __restrict__ res,
                             float* __restrict__ C, int M, int N, int K) {
    __shared__ float As[16][64];
    __shared__ float Bs[16][64];
    const int tid = threadIdx.x;      // 256 threads
    const int tn = tid & 15;          // n sub-tile
    const int tm = tid >> 4;          // m sub-tile
    const int m0 = blockIdx.y * 64;
    const int n0 = blockIdx.x * 64;
    float acc[4][4] = {};
    const int nk = (K + 15) >> 4;
    for (int kt = 0; kt < nk; ++kt) {
        const int k0 = kt << 4;
        #pragma unroll
        for (int r = 0; r < 4; ++r) {
            int idx = tid + r * 256;
            int am = idx >> 4, ak = idx & 15;
            float v = 0.f;
            if (m0 + am < M && k0 + ak < K) v = A[(size_t)(m0 + am) * K + k0 + ak];
            As[ak][am] = v;
        }
        #pragma unroll
        for (int r = 0; r < 4; ++r) {
            int idx = tid + r * 256;
            int bk = idx >> 6, bn = idx & 63;
            float v = 0.f;
            if (k0 + bk < K && n0 + bn < N) v = B[(size_t)(k0 + bk) * N + n0 + bn];
            Bs[bk][bn] = v;
        }
        __syncthreads();
        #pragma unroll
        for (int kk = 0; kk < 16; ++kk) {
            float a[4], b[4];
            #pragma unroll
            for (int i = 0; i < 4; ++i) a[i] = As[kk][tm * 4 + i];
            #pragma unroll
            for (int j = 0; j < 4; ++j) b[j] = Bs[kk][tn * 4 + j];
            #pragma unroll
            for (int i = 0; i < 4; ++i)
                #pragma unroll
                for (int j = 0; j < 4; ++j)
                    acc[i][j] += a[i] * b[j];
        }
        __syncthreads();
    }
    #pragma unroll
    for (int i = 0; i < 4; ++i) {
        int m = m0 + tm * 4 + i;
        if (m >= M) continue;
        #pragma unroll
        for (int j = 0; j < 4; ++j) {
            int n = n0 + tn * 4 + j;
            if (n >= N) continue;
            float v = acc[i][j];
            if (bias) v += bias[n];
            if (res)  v += res[(size_t)m * N + n];
            if (RELU) v = fmaxf(v, 0.f);
            C[(size_t)m * N + n] = v;
        }
    }
}

// ---------------- positional encoding add ----------------
__global__ void add_pe_kernel(float* __restrict__ h) {
    int i = blockIdx.x * blockDim.x + threadIdx.x;
    if (i >= MM * DD) return;
    int d = i % DD;
    int s = (i / DD) % SS;
    // ang = s / 10000^(2d/D), fp32 like the reference
    float denom = powf(10000.0f, 2.0f * (float)d / (float)DD);
    float ang = (float)s / denom;
    h[i] += (d & 1) ? cosf(ang) : sinf(ang);
}

// ---------------- pack per-layer QKV weights: [H,D,DK]x3 -> [D, 672] ----------------
__global__ void pack_qkv_kernel(const float* __restrict__ Wq, const float* __restrict__ Wk,
                                const float* __restrict__ Wv,
                                const float* __restrict__ bq, const float* __restrict__ bk,
                                const float* __restrict__ bv) {
    int i = blockIdx.x * blockDim.x + threadIdx.x;
    if (i < DD * (HH * DKK)) {
        int d = i / (HH * DKK);
        int c = i % (HH * DKK);
        int h = c / DKK, kk = c % DKK;
        int src = (h * DD + d) * DKK + kk;
        g_wqkv[d * QKVN + c]               = Wq[src];
        g_wqkv[d * QKVN + (HH * DKK) + c]  = Wk[src];
        g_wqkv[d * QKVN + 2*(HH * DKK) + c] = Wv[src];
    }
    if (i < HH * DKK) {
        g_bqkv[i]                = bq[i];
        g_bqkv[(HH*DKK) + i]     = bk[i];
        g_bqkv[2*(HH*DKK) + i]   = bv[i];
    }
}

// ---------------- fused causal attention (online softmax) ----------------
// qkv: [B*S, 672] (Q | K | V, each [H,DK] packed). out ctx: [B*S, 224] as (b,q,h,k)
__global__ void attn_kernel(const float* __restrict__ qkv, float* __restrict__ ctx) {
    const int qt = blockIdx.x;            // query tile (64)
    const int bh = blockIdx.y;            // b*H + h
    const int b = bh / HH, h = bh % HH;
    const int tid = threadIdx.x;          // 64 threads, one query each
    const int qidx = qt * 64 + tid;

    __shared__ float Ks[64][DKK];
    __shared__ float Vs[64][DKK];

    const float scale = rsqrtf((float)DKK);
    float q[DKK], o[DKK];
    const float* qrow = qkv + ((size_t)(b * SS + qidx)) * QKVN + h * DKK;
    #pragma unroll
    for (int k = 0; k < DKK; ++k) { q[k] = qrow[k] * scale; o[k] = 0.f; }
    float m = -INFINITY, l = 0.f;

    for (int t = 0; t <= qt; ++t) {
        int s = t * 64 + tid;
        const float* krow = qkv + ((size_t)(b * SS + s)) * QKVN + (HH*DKK) + h * DKK;
        const float* vrow = qkv + ((size_t)(b * SS + s)) * QKVN + 2*(HH*DKK) + h * DKK;
        #pragma unroll
        for (int k = 0; k < DKK; ++k) { Ks[tid][k] = krow[k]; Vs[tid][k] = vrow[k]; }
        __syncthreads();
        const int jmax = (t == qt) ? tid : 63;
        for (int j = 0; j <= jmax; ++j) {
            float sdot = 0.f;
            #pragma unroll
            for (int k = 0; k < DKK; ++k) sdot += q[k] * Ks[j][k];
            float mn = fmaxf(m, sdot);
            float sc = __expf(m - mn);
            float p  = __expf(sdot - mn);
            l = l * sc + p;
            m = mn;
            #pragma unroll
            for (int k = 0; k < DKK; ++k) o[k] = o[k] * sc + p * Vs[j][k];
        }
        __syncthreads();
    }
    float inv = 1.0f / l;
    float* out = ctx + ((size_t)(b * SS + qidx)) * DD + h * DKK;
    #pragma unroll
    for (int k = 0; k < DKK; ++k) out[k] = o[k] * inv;
}

// ---------------- LayerNorm over (S,D) per batch: 3 kernels ----------------
__global__ void ln_partial_kernel(const float* __restrict__ x) {
    const int b = blockIdx.y, g = blockIdx.x;   // 64 chunks per batch
    const int chunk = SD / 64;                  // 3584
    const float* p = x + (size_t)b * SD + (size_t)g * chunk;
    float s = 0.f, ss = 0.f;
    for (int i = threadIdx.x; i < chunk; i += 256) {
        float v = p[i];
        s += v; ss += v * v;
    }
    __shared__ float rs[256], rss[256];
    rs[threadIdx.x] = s; rss[threadIdx.x] = ss;
    __syncthreads();
    for (int o = 128; o > 0; o >>= 1) {
        if (threadIdx.x < o) { rs[threadIdx.x] += rs[threadIdx.x+o]; rss[threadIdx.x] += rss[threadIdx.x+o]; }
        __syncthreads();
    }
    if (threadIdx.x == 0) g_part[b * 64 + g] = make_float2(rs[0], rss[0]);
}

__global__ void ln_final_kernel() {
    const int b = blockIdx.x, t = threadIdx.x;  // 32 threads
    float2 p0 = g_part[b * 64 + t];
    float2 p1 = g_part[b * 64 + t + 32];
    float s = p0.x + p1.x, ss = p0.y + p1.y;
    #pragma unroll
    for (int o = 16; o > 0; o >>= 1) {
        s  += __shfl_down_sync(0xffffffffu, s,  o);
        ss += __shfl_down_sync(0xffffffffu, ss, o);
    }
    if (t == 0) {
        float mu = s / (float)SD;
        float var = ss / (float)SD - mu * mu;
        g_stats[b] = make_float2(mu, rsqrtf(var + 1e-5f));
    }
}

__global__ void ln_norm_kernel(const float* __restrict__ x, const float* __restrict__ w,
                               const float* __restrict__ bw, float* __restrict__ out) {
    int i = blockIdx.x * blockDim.x + threadIdx.x;
    if (i >= BB * SD) return;
    int b = i / SD;
    int sd = i % SD;
    float2 st = g_stats[b];
    out[i] = (x[i] - st.x) * st.y * w[sd] + bw[sd];
}

// ---------------- row softmax over V (in-place on d_out) ----------------
__global__ void softmax_kernel(float* __restrict__ x) {
    const int row = blockIdx.x;
    float* p = x + (size_t)row * VV;
    __shared__ float red[256];
    float mx = -INFINITY;
    for (int i = threadIdx.x; i < VV; i += 256) mx = fmaxf(mx, p[i]);
    red[threadIdx.x] = mx; __syncthreads();
    for (int o = 128; o > 0; o >>= 1) {
        if (threadIdx.x < o) red[threadIdx.x] = fmaxf(red[threadIdx.x], red[threadIdx.x + o]);
        __syncthreads();
    }
    mx = red[0]; __syncthreads();
    float sum = 0.f;
    for (int i = threadIdx.x; i < VV; i += 256) {
        float e = expf(p[i] - mx);
        p[i] = e;
        sum += e;
    }
    red[threadIdx.x] = sum; __syncthreads();
    for (int o = 128; o > 0; o >>= 1) {
        if (threadIdx.x < o) red[threadIdx.x] += red[threadIdx.x + o];
        __syncthreads();
    }
    float inv = 1.0f / red[0];
    for (int i = threadIdx.x; i < VV; i += 256) p[i] *= inv;
}

// ---------------- host-side orchestration ----------------
static inline void run_gemm(const float* A, const float* B, const float* bias,
                            const float* res, float* C, int M, int N, int K, bool relu) {
    dim3 grid((N + 63) / 64, (M + 63) / 64);
    if (relu) sgemm_kernel<true><<<grid, 256>>>(A, B, bias, res, C, M, N, K);
    else      sgemm_kernel<false><<<grid, 256>>>(A, B, bias, res, C, M, N, K);
}

static inline void run_ln(const float* x, const float* w, const float* bw, float* out) {
    dim3 pg(64, BB);
    ln_partial_kernel<<<pg, 256>>>(x);
    ln_final_kernel<<<BB, 32>>>();
    ln_norm_kernel<<<(BB * SD + 255) / 256, 256>>>(x, w, bw, out);
}

extern "C" void kernel_launch(void* const* d_in, const int* in_sizes, int n_in,
                              void* d_out, int out_size) {
    const float* x   = (const float*)d_in[0];
    const float* Wp  = (const float*)d_in[1];
    const float* bp  = (const float*)d_in[2];
    const float* Wq  = (const float*)d_in[3];
    const float* bq  = (const float*)d_in[4];
    const float* Wk  = (const float*)d_in[5];
    const float* bk  = (const float*)d_in[6];
    const float* Wv  = (const float*)d_in[7];
    const float* bv  = (const float*)d_in[8];
    const float* Wo  = (const float*)d_in[9];
    const float* bo  = (const float*)d_in[10];
    const float* W1  = (const float*)d_in[11];
    const float* b1  = (const float*)d_in[12];
    const float* W2  = (const float*)d_in[13];
    const float* b2  = (const float*)d_in[14];
    const float* W3  = (const float*)d_in[15];
    const float* b3  = (const float*)d_in[16];
    const float* lnw = (const float*)d_in[17];
    const float* lnb = (const float*)d_in[18];
    const float* Wf  = (const float*)d_in[19];
    const float* bf  = (const float*)d_in[20];
    float* out = (float*)d_out;

    float *p_h, *p_a, *p_ctx, *p_qkv, *p_f1, *p_f2, *p_wqkv, *p_bqkv;
    cudaGetSymbolAddress((void**)&p_h,    g_h);
    cudaGetSymbolAddress((void**)&p_a,    g_a);
    cudaGetSymbolAddress((void**)&p_ctx,  g_ctx);
    cudaGetSymbolAddress((void**)&p_qkv,  g_qkv);
    cudaGetSymbolAddress((void**)&p_f1,   g_f1);
    cudaGetSymbolAddress((void**)&p_f2,   g_f2);
    cudaGetSymbolAddress((void**)&p_wqkv, g_wqkv);
    cudaGetSymbolAddress((void**)&p_bqkv, g_bqkv);

    // 1) input projection + positional encoding
    run_gemm(x, Wp, bp, nullptr, p_h, MM, DD, DIN, false);
    add_pe_kernel<<<(MM * DD + 255) / 256, 256>>>(p_h);

    // 2) transformer layers
    for (int l = 0; l < LL; ++l) {
        const float* Wq_l = Wq + (size_t)l * HH * DD * DKK;
        const float* Wk_l = Wk + (size_t)l * HH * DD * DKK;
        const float* Wv_l = Wv + (size_t)l * HH * DD * DKK;
        const float* bq_l = bq + (size_t)l * HH * DKK;
        const float* bk_l = bk + (size_t)l * HH * DKK;
        const float* bv_l = bv + (size_t)l * HH * DKK;
        const float* Wo_l = Wo + (size_t)l * DD * DD;
        const float* bo_l = bo + (size_t)l * DD;
        const float* W1_l = W1 + (size_t)l * DD * FFD;
        const float* b1_l = b1 + (size_t)l * FFD;
        const float* W2_l = W2 + (size_t)l * FFD * FFD;
        const float* b2_l = b2 + (size_t)l * FFD;
        const float* W3_l = W3 + (size_t)l * FFD * DD;
        const float* b3_l = b3 + (size_t)l * DD;
        const float* lnw_l = lnw + (size_t)l * SD;
        const float* lnb_l = lnb + (size_t)l * SD;

        // pack QKV weights/biases for one combined GEMM
        pack_qkv_kernel<<<(DD * HH * DKK + 255) / 256, 256>>>(Wq_l, Wk_l, Wv_l, bq_l, bk_l, bv_l);
        // QKV projection: [4096,224] @ [224,672]
        run_gemm(p_h, p_wqkv, p_bqkv, nullptr, p_qkv, MM, QKVN, DD, false);
        // fused causal attention
        dim3 ag(SS / 64, BB * HH);
        attn_kernel<<<ag, 64>>>(p_qkv, p_ctx);
        // output proj + residual
        run_gemm(p_ctx, Wo_l, bo_l, p_h, p_a, MM, DD, DD, false);
        // LN -> h
        run_ln(p_a, lnw_l, lnb_l, p_h);
        // FFN
        run_gemm(p_h,  W1_l, b1_l, nullptr, p_f1, MM, FFD, DD,  true);
        run_gemm(p_f1, W2_l, b2_l, nullptr, p_f2, MM, FFD, FFD, true);
        run_gemm(p_f2, W3_l, b3_l, p_h,     p_a,  MM, DD,  FFD, false);
        // LN twice (same params)
        run_ln(p_a,   lnw_l, lnb_l, p_ctx);
        run_ln(p_ctx, lnw_l, lnb_l, p_h);
    }

    // 3) vocab projection (into d_out) + softmax in-place
    run_gemm(p_h, Wf, bf, nullptr, out, MM, VV, DD, false);
    softmax_kernel<<<MM, 256>>>(out);
    (void)in_sizes; (void)n_in; (void)out_size;
}

// round 2
// speedup vs baseline: 1.1117x; 1.1117x over previous
#include <cuda_runtime.h>
#include <math.h>

// ---------------- problem constants ----------------
#define BB   4
#define SS   1024
#define DIN  768
#define DD   224
#define HH   8
#define DKK  28
#define FFD  600
#define VV   8000
#define LL   8
#define MM   (BB*SS)        // 4096 rows
#define SD   (SS*DD)        // 229376 per-batch LN size
#define QKVN (3*HH*DKK)     // 672

// ---------------- device scratch (static, no allocs) ----------------
__device__ float  g_h   [MM*DD];
__device__ float  g_a   [MM*DD];
__device__ float  g_ctx [MM*DD];
__device__ float  g_qkv [MM*QKVN];
__device__ float  g_f1  [MM*FFD];
__device__ float  g_f2  [MM*FFD];
__device__ float  g_wqkv[DD*QKVN];
__device__ float  g_bqkv[QKVN];
__device__ float2 g_part[BB*64];
__device__ float2 g_stats[BB];

// ---------------- 128x128x8 register-blocked SGEMM ----------------
// C[M,N] = A[M,K] @ B[K,N] (+bias[n]) (+res[m,n]) (optional relu)
// Requirements (all satisfied by this model): M % 128 == 0, K % 8 == 0, N % 4 == 0.
template<bool RELU>
__launch_bounds__(256, 2)
__global__ void sgemm128_kernel(const float* __restrict__ A, const float* __restrict__ B,
                                const float* __restrict__ bias, const float* __restrict__ res,
                                float* __restrict__ C, int M, int N, int K) {
    __shared__ float As[2][8][128];   // [buf][k][m]
    __shared__ float Bs[2][8][128];   // [buf][k][n]

    const int tid = threadIdx.x;            // 256 threads
    const int m0  = blockIdx.y * 128;
    const int n0  = blockIdx.x * 128;

    // global->reg staging mapping
    const int arow = tid >> 1;               // 0..127
    const int acol = (tid & 1) * 4;          // 0 or 4
    const int brow = tid >> 5;               // 0..7
    const int bcol = (tid & 31) * 4;         // 0..124

    // compute mapping: 16 x 16 threads, 8x8 micro tile
    const int tm = (tid >> 4) * 8;            // 0..120
    const int tn = (tid & 15) * 8;            // 0..120

    const float* Aptr = A + (size_t)(m0 + arow) * K + acol;
    const bool  bok   = (n0 + bcol) < N;     // N%4==0 -> whole vec in or out
    const float* Bptr = B + (size_t)brow * N + (n0 + bcol);

    float acc[8][8];
    #pragma unroll
    for (int i = 0; i < 8; ++i)
        #pragma unroll
        for (int j = 0; j < 8; ++j) acc[i][j] = 0.f;

    const int nk = K >> 3;

    // prefetch first tile
    float4 ar = *(const float4*)Aptr;
    float4 br = bok ? *(const float4*)Bptr : make_float4(0.f, 0.f, 0.f, 0.f);
    As[0][acol + 0][arow] = ar.x;
    As[0][acol + 1][arow] = ar.y;
    As[0][acol + 2][arow] = ar.z;
    As[0][acol + 3][arow] = ar.w;
    *(float4*)&Bs[0][brow][bcol] = br;
    __syncthreads();

    for (int kt = 0; kt < nk; ++kt) {
        const int cur = kt & 1;
        // stage next tile into registers
        if (kt + 1 < nk) {
            const float* An = Aptr + (kt + 1) * 8;
            ar = *(const float4*)An;
            if (bok) br = *(const float4*)(Bptr + (size_t)(kt + 1) * 8 * N);
        }
        // compute on current buffer
        #pragma unroll
        for (int k = 0; k < 8; ++k) {
            float a[8], b[8];
            *(float4*)&a[0] = *(const float4*)&As[cur][k][tm];
            *(float4*)&a[4] = *(const float4*)&As[cur][k][tm + 4];
            *(float4*)&b[0] = *(const float4*)&Bs[cur][k][tn];
            *(float4*)&b[4] = *(const float4*)&Bs[cur][k][tn + 4];
            #pragma unroll
            for (int i = 0; i < 8; ++i)
                #pragma unroll
                for (int j = 0; j < 8; ++j)
                    acc[i][j] += a[i] * b[j];
        }
        // commit next tile to the other buffer
        if (kt + 1 < nk) {
            const int nxt = cur ^ 1;
            As[nxt][acol + 0][arow] = ar.x;
            As[nxt][acol + 1][arow] = ar.y;
            As[nxt][acol + 2][arow] = ar.z;
            As[nxt][acol + 3][arow] = ar.w;
            *(float4*)&Bs[nxt][brow][bcol] = br;
            __syncthreads();
        }
    }

    // epilogue
    #pragma unroll
    for (int jv = 0; jv < 2; ++jv) {
        const int n = n0 + tn + jv * 4;
        if (n >= N) continue;
        float4 bv = bias ? *(const float4*)(bias + n) : make_float4(0.f, 0.f, 0.f, 0.f);
        #pragma unroll
        for (int i = 0; i < 8; ++i) {
            const int m = m0 + tm + i;
            float4 v;
            v.x = acc[i][jv * 4 + 0] + bv.x;
            v.y = acc[i][jv * 4 + 1] + bv.y;
            v.z = acc[i][jv * 4 + 2] + bv.z;
            v.w = acc[i][jv * 4 + 3] + bv.w;
            if (res) {
                float4 r = *(const float4*)(res + (size_t)m * N + n);
                v.x += r.x; v.y += r.y; v.z += r.z; v.w += r.w;
            }
            if (RELU) {
                v.x = fmaxf(v.x, 0.f); v.y = fmaxf(v.y, 0.f);
                v.z = fmaxf(v.z, 0.f); v.w = fmaxf(v.w, 0.f);
            }
            *(float4*)(C + (size_t)m * N + n) = v;
        }
    }
}

// ---------------- positional encoding add ----------------
__global__ void add_pe_kernel(float* __restrict__ h) {
    int i = blockIdx.x * blockDim.x + threadIdx.x;
    if (i >= MM * DD) return;
    int d = i % DD;
    int s = (i / DD) % SS;
    float denom = powf(10000.0f, 2.0f * (float)d / (float)DD);
    float ang = (float)s / denom;
    h[i] += (d & 1) ? cosf(ang) : sinf(ang);
}

// ---------------- pack per-layer QKV weights: [H,D,DK]x3 -> [D, 672] ----------------
__global__ void pack_qkv_kernel(const float* __restrict__ Wq, const float* __restrict__ Wk,
                                const float* __restrict__ Wv,
                                const float* __restrict__ bq, const float* __restrict__ bk,
                                const float* __restrict__ bv) {
    int i = blockIdx.x * blockDim.x + threadIdx.x;
    if (i < DD * (HH * DKK)) {
        int d = i / (HH * DKK);
        int c = i % (HH * DKK);
        int h = c / DKK, kk = c % DKK;
        int src = (h * DD + d) * DKK + kk;
        g_wqkv[d * QKVN + c]                = Wq[src];
        g_wqkv[d * QKVN + (HH * DKK) + c]   = Wk[src];
        g_wqkv[d * QKVN + 2*(HH * DKK) + c] = Wv[src];
    }
    if (i < HH * DKK) {
        g_bqkv[i]              = bq[i];
        g_bqkv[(HH*DKK) + i]   = bk[i];
        g_bqkv[2*(HH*DKK) + i] = bv[i];
    }
}

// ---------------- fused causal attention (online softmax) ----------------
__global__ void attn_kernel(const float* __restrict__ qkv, float* __restrict__ ctx) {
    const int qt = blockIdx.x;            // query tile (64)
    const int bh = blockIdx.y;            // b*H + h
    const int b = bh / HH, h = bh % HH;
    const int tid = threadIdx.x;          // 64 threads, one query each
    const int qidx = qt * 64 + tid;

    __shared__ float Ks[64][DKK];
    __shared__ float Vs[64][DKK];

    const float scale = rsqrtf((float)DKK);
    float q[DKK], o[DKK];
    const float* qrow = qkv + ((size_t)(b * SS + qidx)) * QKVN + h * DKK;
    #pragma unroll
    for (int k = 0; k < DKK; ++k) { q[k] = qrow[k] * scale; o[k] = 0.f; }
    float m = -INFINITY, l = 0.f;

    for (int t = 0; t <= qt; ++t) {
        int s = t * 64 + tid;
        const float* krow = qkv + ((size_t)(b * SS + s)) * QKVN + (HH*DKK) + h * DKK;
        const float* vrow = qkv + ((size_t)(b * SS + s)) * QKVN + 2*(HH*DKK) + h * DKK;
        #pragma unroll
        for (int k = 0; k < DKK; ++k) { Ks[tid][k] = krow[k]; Vs[tid][k] = vrow[k]; }
        __syncthreads();
        const int jmax = (t == qt) ? tid : 63;
        for (int j = 0; j <= jmax; ++j) {
            float sdot = 0.f;
            #pragma unroll
            for (int k = 0; k < DKK; ++k) sdot += q[k] * Ks[j][k];
            float mn = fmaxf(m, sdot);
            float sc = __expf(m - mn);
            float p  = __expf(sdot - mn);
            l = l * sc + p;
            m = mn;
            #pragma unroll
            for (int k = 0; k < DKK; ++k) o[k] = o[k] * sc + p * Vs[j][k];
        }
        __syncthreads();
    }
    float inv = 1.0f / l;
    float* out = ctx + ((size_t)(b * SS + qidx)) * DD + h * DKK;
    #pragma unroll
    for (int k = 0; k < DKK; ++k) out[k] = o[k] * inv;
}

// ---------------- LayerNorm over (S,D) per batch: 3 kernels ----------------
__global__ void ln_partial_kernel(const float* __restrict__ x) {
    const int b = blockIdx.y, g = blockIdx.x;   // 64 chunks per batch
    const int chunk = SD / 64;                  // 3584
    const float* p = x + (size_t)b * SD + (size_t)g * chunk;
    float s = 0.f, ss = 0.f;
    for (int i = threadIdx.x; i < chunk; i += 256) {
        float v = p[i];
        s += v; ss += v * v;
    }
    __shared__ float rs[256], rss[256];
    rs[threadIdx.x] = s; rss[threadIdx.x] = ss;
    __syncthreads();
    for (int o = 128; o > 0; o >>= 1) {
        if (threadIdx.x < o) { rs[threadIdx.x] += rs[threadIdx.x+o]; rss[threadIdx.x] += rss[threadIdx.x+o]; }
        __syncthreads();
    }
    if (threadIdx.x == 0) g_part[b * 64 + g] = make_float2(rs[0], rss[0]);
}

__global__ void ln_final_kernel() {
    const int b = blockIdx.x, t = threadIdx.x;  // 32 threads
    float2 p0 = g_part[b * 64 + t];
    float2 p1 = g_part[b * 64 + t + 32];
    float s = p0.x + p1.x, ss = p0.y + p1.y;
    #pragma unroll
    for (int o = 16; o > 0; o >>= 1) {
        s  += __shfl_down_sync(0xffffffffu, s,  o);
        ss += __shfl_down_sync(0xffffffffu, ss, o);
    }
    if (t == 0) {
        float mu = s / (float)SD;
        float var = ss / (float)SD - mu * mu;
        g_stats[b] = make_float2(mu, rsqrtf(var + 1e-5f));
    }
}

__global__ void ln_norm_kernel(const float* __restrict__ x, const float* __restrict__ w,
                               const float* __restrict__ bw, float* __restrict__ out) {
    int i = blockIdx.x * blockDim.x + threadIdx.x;
    if (i >= BB * SD) return;
    int b = i / SD;
    int sd = i % SD;
    float2 st = g_stats[b];
    out[i] = (x[i] - st.x) * st.y * w[sd] + bw[sd];
}

// ---------------- row softmax over V (in-place on d_out) ----------------
__global__ void softmax_kernel(float* __restrict__ x) {
    const int row = blockIdx.x;
    float* p = x + (size_t)row * VV;
    __shared__ float red[256];
    float mx = -INFINITY;
    for (int i = threadIdx.x; i < VV; i += 256) mx = fmaxf(mx, p[i]);
    red[threadIdx.x] = mx; __syncthreads();
    for (int o = 128; o > 0; o >>= 1) {
        if (threadIdx.x < o) red[threadIdx.x] = fmaxf(red[threadIdx.x], red[threadIdx.x + o]);
        __syncthreads();
    }
    mx = red[0]; __syncthreads();
    float sum = 0.f;
    for (int i = threadIdx.x; i < VV; i += 256) {
        float e = expf(p[i] - mx);
        p[i] = e;
        sum += e;
    }
    red[threadIdx.x] = sum; __syncthreads();
    for (int o = 128; o > 0; o >>= 1) {
        if (threadIdx.x < o) red[threadIdx.x] += red[threadIdx.x + o];
        __syncthreads();
    }
    float inv = 1.0f / red[0];
    for (int i = threadIdx.x; i < VV; i += 256) p[i] *= inv;
}

// ---------------- host-side orchestration ----------------
static inline void run_gemm(const float* A, const float* B, const float* bias,
                            const float* res, float* C, int M, int N, int K, bool relu) {
    dim3 grid((N + 127) / 128, M / 128);
    if (relu) sgemm128_kernel<true><<<grid, 256>>>(A, B, bias, res, C, M, N, K);
    else      sgemm128_kernel<false><<<grid, 256>>>(A, B, bias, res, C, M, N, K);
}

static inline void run_ln(const float* x, const float* w, const float* bw, float* out) {
    dim3 pg(64, BB);
    ln_partial_kernel<<<pg, 256>>>(x);
    ln_final_kernel<<<BB, 32>>>();
    ln_norm_kernel<<<(BB * SD + 255) / 256, 256>>>(x, w, bw, out);
}

extern "C" void kernel_launch(void* const* d_in, const int* in_sizes, int n_in,
                              void* d_out, int out_size) {
    const float* x   = (const float*)d_in[0];
    const float* Wp  = (const float*)d_in[1];
    const float* bp  = (const float*)d_in[2];
    const float* Wq  = (const float*)d_in[3];
    const float* bq  = (const float*)d_in[4];
    const float* Wk  = (const float*)d_in[5];
    const float* bk  = (const float*)d_in[6];
    const float* Wv  = (const float*)d_in[7];
    const float* bv  = (const float*)d_in[8];
    const float* Wo  = (const float*)d_in[9];
    const float* bo  = (const float*)d_in[10];
    const float* W1  = (const float*)d_in[11];
    const float* b1  = (const float*)d_in[12];
    const float* W2  = (const float*)d_in[13];
    const float* b2  = (const float*)d_in[14];
    const float* W3  = (const float*)d_in[15];
    const float* b3  = (const float*)d_in[16];
    const float* lnw = (const float*)d_in[17];
    const float* lnb = (const float*)d_in[18];
    const float* Wf  = (const float*)d_in[19];
    const float* bf  = (const float*)d_in[20];
    float* out = (float*)d_out;

    float *p_h, *p_a, *p_ctx, *p_qkv, *p_f1, *p_f2, *p_wqkv, *p_bqkv;
    cudaGetSymbolAddress((void**)&p_h,    g_h);
    cudaGetSymbolAddress((void**)&p_a,    g_a);
    cudaGetSymbolAddress((void**)&p_ctx,  g_ctx);
    cudaGetSymbolAddress((void**)&p_qkv,  g_qkv);
    cudaGetSymbolAddress((void**)&p_f1,   g_f1);
    cudaGetSymbolAddress((void**)&p_f2,   g_f2);
    cudaGetSymbolAddress((void**)&p_wqkv, g_wqkv);
    cudaGetSymbolAddress((void**)&p_bqkv, g_bqkv);

    // 1) input projection + positional encoding
    run_gemm(x, Wp, bp, nullptr, p_h, MM, DD, DIN, false);
    add_pe_kernel<<<(MM * DD + 255) / 256, 256>>>(p_h);

    // 2) transformer layers
    for (int l = 0; l < LL; ++l) {
        const float* Wq_l = Wq + (size_t)l * HH * DD * DKK;
        const float* Wk_l = Wk + (size_t)l * HH * DD * DKK;
        const float* Wv_l = Wv + (size_t)l * HH * DD * DKK;
        const float* bq_l = bq + (size_t)l * HH * DKK;
        const float* bk_l = bk + (size_t)l * HH * DKK;
        const float* bv_l = bv + (size_t)l * HH * DKK;
        const float* Wo_l = Wo + (size_t)l * DD * DD;
        const float* bo_l = bo + (size_t)l * DD;
        const float* W1_l = W1 + (size_t)l * DD * FFD;
        const float* b1_l = b1 + (size_t)l * FFD;
        const float* W2_l = W2 + (size_t)l * FFD * FFD;
        const float* b2_l = b2 + (size_t)l * FFD;
        const float* W3_l = W3 + (size_t)l * FFD * DD;
        const float* b3_l = b3 + (size_t)l * DD;
        const float* lnw_l = lnw + (size_t)l * SD;
        const float* lnb_l = lnb + (size_t)l * SD;

        pack_qkv_kernel<<<(DD * HH * DKK + 255) / 256, 256>>>(Wq_l, Wk_l, Wv_l, bq_l, bk_l, bv_l);
        run_gemm(p_h, p_wqkv, p_bqkv, nullptr, p_qkv, MM, QKVN, DD, false);
        dim3 ag(SS / 64, BB * HH);
        attn_kernel<<<ag, 64>>>(p_qkv, p_ctx);
        run_gemm(p_ctx, Wo_l, bo_l, p_h, p_a, MM, DD, DD, false);
        run_ln(p_a, lnw_l, lnb_l, p_h);
        run_gemm(p_h,  W1_l, b1_l, nullptr, p_f1, MM, FFD, DD,  true);
        run_gemm(p_f1, W2_l, b2_l, nullptr, p_f2, MM, FFD, FFD, true);
        run_gemm(p_f2, W3_l, b3_l, p_h,     p_a,  MM, DD,  FFD, false);
        run_ln(p_a,   lnw_l, lnb_l, p_ctx);
        run_ln(p_ctx, lnw_l, lnb_l, p_h);
    }

    // 3) vocab projection (into d_out) + softmax in-place
    run_gemm(p_h, Wf, bf, nullptr, out, MM, VV, DD, false);
    softmax_kernel<<<MM, 256>>>(out);
    (void)in_sizes; (void)n_in; (void)out_size;
}

// round 3
// speedup vs baseline: 1.2780x; 1.1496x over previous
#include <cuda_runtime.h>
#include <math.h>
#include <stdint.h>

// ---------------- problem constants ----------------
#define BB   4
#define SS   1024
#define DIN  768
#define DD   224
#define HH   8
#define DKK  28
#define FFD  600
#define VV   8000
#define LL   8
#define MM   (BB*SS)        // 4096 rows
#define SD   (SS*DD)        // 229376 per-batch LN size
#define QKVN (3*HH*DKK)     // 672

// ---------------- device scratch (static, no allocs) ----------------
__device__ float  g_h   [MM*DD];
__device__ float  g_a   [MM*DD];
__device__ float  g_ctx [MM*DD];
__device__ float  g_qkv [MM*QKVN];
__device__ float  g_f1  [MM*FFD];
__device__ float  g_f2  [MM*FFD];
__device__ float  g_wqkv[DD*QKVN];
__device__ float  g_bqkv[QKVN];
__device__ float2 g_part[BB*64];
__device__ float2 g_stats[BB];

// ---------------- helpers ----------------
__device__ __forceinline__ uint32_t f2tf32(float x) {
    uint32_t r;
    asm("cvt.rna.tf32.f32 %0, %1;" : "=r"(r) : "f"(x));
    return r;
}

__device__ __forceinline__ void mma_tf32(float* c, uint32_t a0, uint32_t a1,
                                         uint32_t a2, uint32_t a3,
                                         uint32_t b0, uint32_t b1) {
    asm volatile(
        "mma.sync.aligned.m16n8k8.row.col.f32.tf32.tf32.f32 "
        "{%0,%1,%2,%3}, {%4,%5,%6,%7}, {%8,%9}, {%0,%1,%2,%3};"
        : "+f"(c[0]), "+f"(c[1]), "+f"(c[2]), "+f"(c[3])
        : "r"(a0), "r"(a1), "r"(a2), "r"(a3), "r"(b0), "r"(b1));
}

// ---------------- tf32x3 tensor-core GEMM ----------------
// C[M,N] = A[M,K] @ B[K,N] (+bias) (+res) (optional relu)
// Requirements: M % 128 == 0, K % 8 == 0, N % 4 == 0. (all hold here)
// Block: 128x128, 8 warps, warp tile 64x32 (4 m-tiles x 4 n-tiles of m16n8k8).
#define A_STR 12
#define B_STR 136
template<bool RELU>
__launch_bounds__(256)
__global__ void tgemm_kernel(const float* __restrict__ A, const float* __restrict__ B,
                             const float* __restrict__ bias, const float* __restrict__ res,
                             float* __restrict__ C, int M, int N, int K) {
    __shared__ float As[2][128][A_STR];   // [buf][m][k]   (k-tile = 8)
    __shared__ float Bs[2][8][B_STR];     // [buf][k][n]

    const int tid  = threadIdx.x;
    const int lane = tid & 31;
    const int w    = tid >> 5;
    const int m0   = blockIdx.y * 128;
    const int n0   = blockIdx.x * 128;

    const int wm = (w >> 2) * 64;    // 0 / 64
    const int wn = (w & 3) * 32;     // 0,32,64,96
    const int fr = lane >> 2;        // 0..7
    const int fc = lane & 3;         // 0..3

    // global staging mapping
    const int arow = tid >> 1;            // 0..127
    const int acol = (tid & 1) * 4;       // 0 / 4
    const int brow = tid >> 5;            // 0..7
    const int bcol = (tid & 31) * 4;      // 0..124
    const bool bok = (n0 + bcol) < N;

    const float* Aptr = A + (size_t)(m0 + arow) * K + acol;
    const float* Bptr = B + (size_t)brow * N + (n0 + bcol);

    float acc[4][4][4];
    #pragma unroll
    for (int i = 0; i < 4; ++i)
        #pragma unroll
        for (int j = 0; j < 4; ++j)
            #pragma unroll
            for (int r = 0; r < 4; ++r) acc[i][j][r] = 0.f;

    const int nk = K >> 3;

    // prefetch tile 0
    float4 ar = *(const float4*)Aptr;
    float4 br = bok ? *(const float4*)Bptr : make_float4(0.f, 0.f, 0.f, 0.f);
    *(float4*)&As[0][arow][acol] = ar;
    *(float4*)&Bs[0][brow][bcol] = br;
    __syncthreads();

    for (int kt = 0; kt < nk; ++kt) {
        const int cur = kt & 1;
        if (kt + 1 < nk) {
            ar = *(const float4*)(Aptr + (kt + 1) * 8);
            br = bok ? *(const float4*)(Bptr + (size_t)(kt + 1) * 8 * N)
                     : make_float4(0.f, 0.f, 0.f, 0.f);
        }

        // load + split fragments
        uint32_t ah[4][4], al[4][4], bh[4][2], bl[4][2];
        #pragma unroll
        for (int i = 0; i < 4; ++i) {
            const int mb = wm + i * 16;
            float v0 = As[cur][mb + fr][fc];
            float v1 = As[cur][mb + 8 + fr][fc];
            float v2 = As[cur][mb + fr][fc + 4];
            float v3 = As[cur][mb + 8 + fr][fc + 4];
            ah[i][0] = f2tf32(v0); al[i][0] = f2tf32(v0 - __uint_as_float(ah[i][0]));
            ah[i][1] = f2tf32(v1); al[i][1] = f2tf32(v1 - __uint_as_float(ah[i][1]));
            ah[i][2] = f2tf32(v2); al[i][2] = f2tf32(v2 - __uint_as_float(ah[i][2]));
            ah[i][3] = f2tf32(v3); al[i][3] = f2tf32(v3 - __uint_as_float(ah[i][3]));
        }
        #pragma unroll
        for (int j = 0; j < 4; ++j) {
            const int nb = wn + j * 8 + fr;
            float v0 = Bs[cur][fc][nb];
            float v1 = Bs[cur][fc + 4][nb];
            bh[j][0] = f2tf32(v0); bl[j][0] = f2tf32(v0 - __uint_as_float(bh[j][0]));
            bh[j][1] = f2tf32(v1); bl[j][1] = f2tf32(v1 - __uint_as_float(bh[j][1]));
        }

        // 3xTF32 mma
        #pragma unroll
        for (int i = 0; i < 4; ++i)
            #pragma unroll
            for (int j = 0; j < 4; ++j) {
                mma_tf32(acc[i][j], ah[i][0], ah[i][1], ah[i][2], ah[i][3], bl[j][0], bl[j][1]);
                mma_tf32(acc[i][j], al[i][0], al[i][1], al[i][2], al[i][3], bh[j][0], bh[j][1]);
                mma_tf32(acc[i][j], ah[i][0], ah[i][1], ah[i][2], ah[i][3], bh[j][0], bh[j][1]);
            }

        if (kt + 1 < nk) {
            const int nxt = cur ^ 1;
            *(float4*)&As[nxt][arow][acol] = ar;
            *(float4*)&Bs[nxt][brow][bcol] = br;
            __syncthreads();
        }
    }

    // epilogue: c0,c1 -> (row, col..col+1), c2,c3 -> (row+8, col..col+1)
    #pragma unroll
    for (int i = 0; i < 4; ++i) {
        const int r0 = m0 + wm + i * 16 + fr;
        const int r1 = r0 + 8;
        #pragma unroll
        for (int j = 0; j < 4; ++j) {
            const int cb = n0 + wn + j * 8 + 2 * fc;
            if (cb >= N) continue;
            float bx = 0.f, by = 0.f;
            if (bias) { bx = bias[cb]; by = bias[cb + 1]; }
            float2 v0, v1;
            v0.x = acc[i][j][0] + bx; v0.y = acc[i][j][1] + by;
            v1.x = acc[i][j][2] + bx; v1.y = acc[i][j][3] + by;
            if (res) {
                float2 q0 = *(const float2*)(res + (size_t)r0 * N + cb);
                float2 q1 = *(const float2*)(res + (size_t)r1 * N + cb);
                v0.x += q0.x; v0.y += q0.y; v1.x += q1.x; v1.y += q1.y;
            }
            if (RELU) {
                v0.x = fmaxf(v0.x, 0.f); v0.y = fmaxf(v0.y, 0.f);
                v1.x = fmaxf(v1.x, 0.f); v1.y = fmaxf(v1.y, 0.f);
            }
            *(float2*)(C + (size_t)r0 * N + cb) = v0;
            *(float2*)(C + (size_t)r1 * N + cb) = v1;
        }
    }
}

// ---------------- positional encoding add ----------------
__global__ void add_pe_kernel(float* __restrict__ h) {
    int i = blockIdx.x * blockDim.x + threadIdx.x;
    if (i >= MM * DD) return;
    int d = i % DD;
    int s = (i / DD) % SS;
    float denom = powf(10000.0f, 2.0f * (float)d / (float)DD);
    float ang = (float)s / denom;
    h[i] += (d & 1) ? cosf(ang) : sinf(ang);
}

// ---------------- pack per-layer QKV weights ----------------
__global__ void pack_qkv_kernel(const float* __restrict__ Wq, const float* __restrict__ Wk,
                                const float* __restrict__ Wv,
                                const float* __restrict__ bq, const float* __restrict__ bk,
                                const float* __restrict__ bv) {
    int i = blockIdx.x * blockDim.x + threadIdx.x;
    if (i < DD * (HH * DKK)) {
        int d = i / (HH * DKK);
        int c = i % (HH * DKK);
        int h = c / DKK, kk = c % DKK;
        int src = (h * DD + d) * DKK + kk;
        g_wqkv[d * QKVN + c]                = Wq[src];
        g_wqkv[d * QKVN + (HH * DKK) + c]   = Wk[src];
        g_wqkv[d * QKVN + 2*(HH * DKK) + c] = Wv[src];
    }
    if (i < HH * DKK) {
        g_bqkv[i]              = bq[i];
        g_bqkv[(HH*DKK) + i]   = bk[i];
        g_bqkv[2*(HH*DKK) + i] = bv[i];
    }
}

// ---------------- fused causal attention (online softmax) ----------------
__global__ void attn_kernel(const float* __restrict__ qkv, float* __restrict__ ctx) {
    const int qt = blockIdx.x;
    const int bh = blockIdx.y;
    const int b = bh / HH, h = bh % HH;
    const int tid = threadIdx.x;
    const int qidx = qt * 64 + tid;

    __shared__ float Ks[64][DKK];
    __shared__ float Vs[64][DKK];

    const float scale = rsqrtf((float)DKK);
    float q[DKK], o[DKK];
    const float* qrow = qkv + ((size_t)(b * SS + qidx)) * QKVN + h * DKK;
    #pragma unroll
    for (int k = 0; k < DKK; ++k) { q[k] = qrow[k] * scale; o[k] = 0.f; }
    float m = -INFINITY, l = 0.f;

    for (int t = 0; t <= qt; ++t) {
        int s = t * 64 + tid;
        const float* krow = qkv + ((size_t)(b * SS + s)) * QKVN + (HH*DKK) + h * DKK;
        const float* vrow = qkv + ((size_t)(b * SS + s)) * QKVN + 2*(HH*DKK) + h * DKK;
        #pragma unroll
        for (int k = 0; k < DKK; ++k) { Ks[tid][k] = krow[k]; Vs[tid][k] = vrow[k]; }
        __syncthreads();
        const int jmax = (t == qt) ? tid : 63;
        for (int j = 0; j <= jmax; ++j) {
            float sdot = 0.f;
            #pragma unroll
            for (int k = 0; k < DKK; ++k) sdot += q[k] * Ks[j][k];
            float mn = fmaxf(m, sdot);
            float sc = __expf(m - mn);
            float p  = __expf(sdot - mn);
            l = l * sc + p;
            m = mn;
            #pragma unroll
            for (int k = 0; k < DKK; ++k) o[k] = o[k] * sc + p * Vs[j][k];
        }
        __syncthreads();
    }
    float inv = 1.0f / l;
    float* out = ctx + ((size_t)(b * SS + qidx)) * DD + h * DKK;
    #pragma unroll
    for (int k = 0; k < DKK; ++k) out[k] = o[k] * inv;
}

// ---------------- LayerNorm over (S,D) per batch ----------------
__global__ void ln_partial_kernel(const float* __restrict__ x) {
    const int b = blockIdx.y, g = blockIdx.x;
    const int chunk = SD / 64;
    const float* p = x + (size_t)b * SD + (size_t)g * chunk;
    float s = 0.f, ss = 0.f;
    for (int i = threadIdx.x; i < chunk; i += 256) {
        float v = p[i];
        s += v; ss += v * v;
    }
    __shared__ float rs[256], rss[256];
    rs[threadIdx.x] = s; rss[threadIdx.x] = ss;
    __syncthreads();
    for (int o = 128; o > 0; o >>= 1) {
        if (threadIdx.x < o) { rs[threadIdx.x] += rs[threadIdx.x+o]; rss[threadIdx.x] += rss[threadIdx.x+o]; }
        __syncthreads();
    }
    if (threadIdx.x == 0) g_part[b * 64 + g] = make_float2(rs[0], rss[0]);
}

__global__ void ln_final_kernel() {
    const int b = blockIdx.x, t = threadIdx.x;
    float2 p0 = g_part[b * 64 + t];
    float2 p1 = g_part[b * 64 + t + 32];
    float s = p0.x + p1.x, ss = p0.y + p1.y;
    #pragma unroll
    for (int o = 16; o > 0; o >>= 1) {
        s  += __shfl_down_sync(0xffffffffu, s,  o);
        ss += __shfl_down_sync(0xffffffffu, ss, o);
    }
    if (t == 0) {
        float mu = s / (float)SD;
        float var = ss / (float)SD - mu * mu;
        g_stats[b] = make_float2(mu, rsqrtf(var + 1e-5f));
    }
}

__global__ void ln_norm_kernel(const float* __restrict__ x, const float* __restrict__ w,
                               const float* __restrict__ bw, float* __restrict__ out) {
    int i = blockIdx.x * blockDim.x + threadIdx.x;
    if (i >= BB * SD) return;
    int b = i / SD;
    int sd = i % SD;
    float2 st = g_stats[b];
    out[i] = (x[i] - st.x) * st.y * w[sd] + bw[sd];
}

// ---------------- row softmax over V (in-place on d_out) ----------------
__global__ void softmax_kernel(float* __restrict__ x) {
    const int row = blockIdx.x;
    float* p = x + (size_t)row * VV;
    __shared__ float red[256];
    float mx = -INFINITY;
    for (int i = threadIdx.x; i < VV; i += 256) mx = fmaxf(mx, p[i]);
    red[threadIdx.x] = mx; __syncthreads();
    for (int o = 128; o > 0; o >>= 1) {
        if (threadIdx.x < o) red[threadIdx.x] = fmaxf(red[threadIdx.x], red[threadIdx.x + o]);
        __syncthreads();
    }
    mx = red[0]; __syncthreads();
    float sum = 0.f;
    for (int i = threadIdx.x; i < VV; i += 256) {
        float e = expf(p[i] - mx);
        p[i] = e;
        sum += e;
    }
    red[threadIdx.x] = sum; __syncthreads();
    for (int o = 128; o > 0; o >>= 1) {
        if (threadIdx.x < o) red[threadIdx.x] += red[threadIdx.x + o];
        __syncthreads();
    }
    float inv = 1.0f / red[0];
    for (int i = threadIdx.x; i < VV; i += 256) p[i] *= inv;
}

// ---------------- host-side orchestration ----------------
static inline void run_gemm(const float* A, const float* B, const float* bias,
                            const float* res, float* C, int M, int N, int K, bool relu) {
    dim3 grid((N + 127) / 128, M / 128);
    if (relu) tgemm_kernel<true><<<grid, 256>>>(A, B, bias, res, C, M, N, K);
    else      tgemm_kernel<false><<<grid, 256>>>(A, B, bias, res, C, M, N, K);
}

static inline void run_ln(const float* x, const float* w, const float* bw, float* out) {
    dim3 pg(64, BB);
    ln_partial_kernel<<<pg, 256>>>(x);
    ln_final_kernel<<<BB, 32>>>();
    ln_norm_kernel<<<(BB * SD + 255) / 256, 256>>>(x, w, bw, out);
}

extern "C" void kernel_launch(void* const* d_in, const int* in_sizes, int n_in,
                              void* d_out, int out_size) {
    const float* x   = (const float*)d_in[0];
    const float* Wp  = (const float*)d_in[1];
    const float* bp  = (const float*)d_in[2];
    const float* Wq  = (const float*)d_in[3];
    const float* bq  = (const float*)d_in[4];
    const float* Wk  = (const float*)d_in[5];
    const float* bk  = (const float*)d_in[6];
    const float* Wv  = (const float*)d_in[7];
    const float* bv  = (const float*)d_in[8];
    const float* Wo  = (const float*)d_in[9];
    const float* bo  = (const float*)d_in[10];
    const float* W1  = (const float*)d_in[11];
    const float* b1  = (const float*)d_in[12];
    const float* W2  = (const float*)d_in[13];
    const float* b2  = (const float*)d_in[14];
    const float* W3  = (const float*)d_in[15];
    const float* b3  = (const float*)d_in[16];
    const float* lnw = (const float*)d_in[17];
    const float* lnb = (const float*)d_in[18];
    const float* Wf  = (const float*)d_in[19];
    const float* bf  = (const float*)d_in[20];
    float* out = (float*)d_out;

    float *p_h, *p_a, *p_ctx, *p_qkv, *p_f1, *p_f2, *p_wqkv, *p_bqkv;
    cudaGetSymbolAddress((void**)&p_h,    g_h);
    cudaGetSymbolAddress((void**)&p_a,    g_a);
    cudaGetSymbolAddress((void**)&p_ctx,  g_ctx);
    cudaGetSymbolAddress((void**)&p_qkv,  g_qkv);
    cudaGetSymbolAddress((void**)&p_f1,   g_f1);
    cudaGetSymbolAddress((void**)&p_f2,   g_f2);
    cudaGetSymbolAddress((void**)&p_wqkv, g_wqkv);
    cudaGetSymbolAddress((void**)&p_bqkv, g_bqkv);

    // 1) input projection + positional encoding
    run_gemm(x, Wp, bp, nullptr, p_h, MM, DD, DIN, false);
    add_pe_kernel<<<(MM * DD + 255) / 256, 256>>>(p_h);

    // 2) transformer layers
    for (int l = 0; l < LL; ++l) {
        const float* Wq_l = Wq + (size_t)l * HH * DD * DKK;
        const float* Wk_l = Wk + (size_t)l * HH * DD * DKK;
        const float* Wv_l = Wv + (size_t)l * HH * DD * DKK;
        const float* bq_l = bq + (size_t)l * HH * DKK;
        const float* bk_l = bk + (size_t)l * HH * DKK;
        const float* bv_l = bv + (size_t)l * HH * DKK;
        const float* Wo_l = Wo + (size_t)l * DD * DD;
        const float* bo_l = bo + (size_t)l * DD;
        const float* W1_l = W1 + (size_t)l * DD * FFD;
        const float* b1_l = b1 + (size_t)l * FFD;
        const float* W2_l = W2 + (size_t)l * FFD * FFD;
        const float* b2_l = b2 + (size_t)l * FFD;
        const float* W3_l = W3 + (size_t)l * FFD * DD;
        const float* b3_l = b3 + (size_t)l * DD;
        const float* lnw_l = lnw + (size_t)l * SD;
        const float* lnb_l = lnb + (size_t)l * SD;

        pack_qkv_kernel<<<(DD * HH * DKK + 255) / 256, 256>>>(Wq_l, Wk_l, Wv_l, bq_l, bk_l, bv_l);
        run_gemm(p_h, p_wqkv, p_bqkv, nullptr, p_qkv, MM, QKVN, DD, false);
        dim3 ag(SS / 64, BB * HH);
        attn_kernel<<<ag, 64>>>(p_qkv, p_ctx);
        run_gemm(p_ctx, Wo_l, bo_l, p_h, p_a, MM, DD, DD, false);
        run_ln(p_a, lnw_l, lnb_l, p_h);
        run_gemm(p_h,  W1_l, b1_l, nullptr, p_f1, MM, FFD, DD,  true);
        run_gemm(p_f1, W2_l, b2_l, nullptr, p_f2, MM, FFD, FFD, true);
        run_gemm(p_f2, W3_l, b3_l, p_h,     p_a,  MM, DD,  FFD, false);
        run_ln(p_a,   lnw_l, lnb_l, p_ctx);
        run_ln(p_ctx, lnw_l, lnb_l, p_h);
    }

    // 3) vocab projection (into d_out) + softmax in-place
    run_gemm(p_h, Wf, bf, nullptr, out, MM, VV, DD, false);
    softmax_kernel<<<MM, 256>>>(out);
    (void)in_sizes; (void)n_in; (void)out_size;
}

// round 4
// speedup vs baseline: 2.1722x; 1.6997x over previous
#include <cuda_runtime.h>
#include <cuda_bf16.h>
#include <math.h>
#include <stdint.h>

// ---------------- problem constants ----------------
#define BB   4
#define SS   1024
#define DIN  768
#define DD   224
#define HH   8
#define DKK  28
#define FFD  600
#define VV   8000
#define LL   8
#define MM   (BB*SS)        // 4096 rows
#define SD   (SS*DD)        // 229376 per-batch LN size
#define QKVN (3*HH*DKK)     // 672

// ---------------- device scratch (static, no allocs) ----------------
__device__ float  g_h   [MM*DD];
__device__ float  g_a   [MM*DD];
__device__ float  g_ctx [MM*DD];
__device__ float  g_qkv [MM*QKVN];
__device__ float  g_f1  [MM*FFD];
__device__ float  g_f2  [MM*FFD];
__device__ float  g_wqkv[DD*QKVN];
__device__ float  g_bqkv[QKVN];
__device__ float2 g_part[BB*64];

// ---------------- helpers ----------------
// split fp32 pair -> packed bf16x2 high word + packed bf16x2 residual word
__device__ __forceinline__ void splitw(float lo, float hi, uint32_t& ph, uint32_t& pl) {
    __nv_bfloat16 lh = __float2bfloat16(lo);
    __nv_bfloat16 hh = __float2bfloat16(hi);
    __nv_bfloat162 vh = __halves2bfloat162(lh, hh);
    __nv_bfloat162 vl = __halves2bfloat162(__float2bfloat16(lo - __bfloat162float(lh)),
                                           __float2bfloat16(hi - __bfloat162float(hh)));
    ph = *reinterpret_cast<uint32_t*>(&vh);
    pl = *reinterpret_cast<uint32_t*>(&vl);
}

__device__ __forceinline__ void mma_bf16(float* c, const uint32_t* a, uint32_t b0, uint32_t b1) {
    asm volatile(
        "mma.sync.aligned.m16n8k16.row.col.f32.bf16.bf16.f32 "
        "{%0,%1,%2,%3}, {%4,%5,%6,%7}, {%8,%9}, {%0,%1,%2,%3};"
        : "+f"(c[0]), "+f"(c[1]), "+f"(c[2]), "+f"(c[3])
        : "r"(a[0]), "r"(a[1]), "r"(a[2]), "r"(a[3]), "r"(b0), "r"(b1));
}

// ---------------- bf16x3 tensor-core GEMM ----------------
// C[M,N] = A[M,K] @ B[K,N] (+bias) (+res) (optional relu)
// M % BM == 0, K % 8 == 0, N % 4 == 0 (all hold here). k-tile = 16 (zero-padded tail).
// Block: BM x 128, 8 warps as 2(M) x 4(N); warp tile (BM/2) x 32.
#define AP 12
#define BP 136
template<int BM, bool RELU>
__launch_bounds__(256)
__global__ void bgemm_kernel(const float* __restrict__ A, const float* __restrict__ B,
                             const float* __restrict__ bias, const float* __restrict__ res,
                             float* __restrict__ C, int M, int N, int K) {
    constexpr int MF = BM / 32;                    // m16 frags per warp
    __shared__ uint32_t Ash[2][BM][AP];            // packed bf16x2, [m][k/2] (cols 0..7)
    __shared__ uint32_t Asl[2][BM][AP];
    __shared__ uint32_t Bsh[2][8][BP];             // packed bf16x2, [k/2][n]
    __shared__ uint32_t Bsl[2][8][BP];

    const int tid  = threadIdx.x;
    const int lane = tid & 31;
    const int w    = tid >> 5;
    const int m0   = blockIdx.y * BM;
    const int n0   = blockIdx.x * 128;

    const int wm = (w >> 2) * (BM / 2);
    const int wn = (w & 3) * 32;
    const int fr = lane >> 2;      // groupID
    const int fc = lane & 3;       // thread-in-group

    // staging mapping
    const int arow = (BM == 128) ? (tid >> 1) : (tid >> 2);
    const int acol = (BM == 128) ? ((tid & 1) * 8) : ((tid & 3) * 4);
    const int bt   = tid >> 5;                 // k-pair row 0..7
    const int bcol = (tid & 31) * 4;
    const bool bok = (n0 + bcol) < N;

    const float* Aptr = A + (size_t)(m0 + arow) * K + acol;
    const float* Bp   = B + (size_t)(2 * bt) * N + n0 + bcol;

    float acc[MF][4][4];
    #pragma unroll
    for (int i = 0; i < MF; ++i)
        #pragma unroll
        for (int j = 0; j < 4; ++j)
            #pragma unroll
            for (int r = 0; r < 4; ++r) acc[i][j][r] = 0.f;

    const int nk = (K + 15) >> 4;

    float4 avA, avB, bv0, bv1;
    const float4 z4 = make_float4(0.f, 0.f, 0.f, 0.f);

    // ---- load tile k0 into registers ----
    auto load_tile = [&](int k0) {
        const bool ak = (k0 + acol) < K;
        avA = ak ? *(const float4*)(Aptr + k0) : z4;
        if (BM == 128) avB = ak ? *(const float4*)(Aptr + k0 + 4) : z4;
        const bool bk = bok && ((k0 + 2 * bt) < K);
        bv0 = bk ? *(const float4*)(Bp + (size_t)k0 * N)     : z4;
        bv1 = bk ? *(const float4*)(Bp + (size_t)k0 * N + N) : z4;
    };
    // ---- convert + commit registers into smem buffer ----
    auto commit_tile = [&](int buf) {
        if (BM == 128) {
            uint32_t h[4], l[4];
            splitw(avA.x, avA.y, h[0], l[0]);
            splitw(avA.z, avA.w, h[1], l[1]);
            splitw(avB.x, avB.y, h[2], l[2]);
            splitw(avB.z, avB.w, h[3], l[3]);
            const int wc = acol >> 1;
            *(uint4*)&Ash[buf][arow][wc] = *(uint4*)h;
            *(uint4*)&Asl[buf][arow][wc] = *(uint4*)l;
        } else {
            uint32_t h[2], l[2];
            splitw(avA.x, avA.y, h[0], l[0]);
            splitw(avA.z, avA.w, h[1], l[1]);
            const int wc = acol >> 1;
            *(uint2*)&Ash[buf][arow][wc] = *(uint2*)h;
            *(uint2*)&Asl[buf][arow][wc] = *(uint2*)l;
        }
        uint32_t bh[4], bl[4];
        splitw(bv0.x, bv1.x, bh[0], bl[0]);
        splitw(bv0.y, bv1.y, bh[1], bl[1]);
        splitw(bv0.z, bv1.z, bh[2], bl[2]);
        splitw(bv0.w, bv1.w, bh[3], bl[3]);
        *(uint4*)&Bsh[buf][bt][bcol] = *(uint4*)bh;
        *(uint4*)&Bsl[buf][bt][bcol] = *(uint4*)bl;
    };

    load_tile(0);
    commit_tile(0);
    __syncthreads();

    for (int kt = 0; kt < nk; ++kt) {
        const int cur = kt & 1;
        if (kt + 1 < nk) load_tile((kt + 1) * 16);

        // fragment loads (packed words, zero conversion)
        uint32_t ah[MF][4], al[MF][4];
        #pragma unroll
        for (int i = 0; i < MF; ++i) {
            const int mb = wm + i * 16;
            ah[i][0] = Ash[cur][mb + fr][fc];
            ah[i][1] = Ash[cur][mb + 8 + fr][fc];
            ah[i][2] = Ash[cur][mb + fr][fc + 4];
            ah[i][3] = Ash[cur][mb + 8 + fr][fc + 4];
            al[i][0] = Asl[cur][mb + fr][fc];
            al[i][1] = Asl[cur][mb + 8 + fr][fc];
            al[i][2] = Asl[cur][mb + fr][fc + 4];
            al[i][3] = Asl[cur][mb + 8 + fr][fc + 4];
        }
        #pragma unroll
        for (int j = 0; j < 4; ++j) {
            const int nb = wn + j * 8 + fr;
            const uint32_t bh0 = Bsh[cur][fc][nb];
            const uint32_t bh1 = Bsh[cur][fc + 4][nb];
            const uint32_t bl0 = Bsl[cur][fc][nb];
            const uint32_t bl1 = Bsl[cur][fc + 4][nb];
            #pragma unroll
            for (int i = 0; i < MF; ++i) {
                mma_bf16(acc[i][j], al[i], bh0, bh1);   // al*bh
                mma_bf16(acc[i][j], ah[i], bl0, bl1);   // ah*bl
                mma_bf16(acc[i][j], ah[i], bh0, bh1);   // ah*bh
            }
        }

        if (kt + 1 < nk) {
            commit_tile(cur ^ 1);
            __syncthreads();
        }
    }

    // epilogue
    #pragma unroll
    for (int i = 0; i < MF; ++i) {
        const int r0 = m0 + wm + i * 16 + fr;
        const int r1 = r0 + 8;
        #pragma unroll
        for (int j = 0; j < 4; ++j) {
            const int cb = n0 + wn + j * 8 + 2 * fc;
            if (cb >= N) continue;
            float bx = 0.f, by = 0.f;
            if (bias) { bx = bias[cb]; by = bias[cb + 1]; }
            float2 v0, v1;
            v0.x = acc[i][j][0] + bx; v0.y = acc[i][j][1] + by;
            v1.x = acc[i][j][2] + bx; v1.y = acc[i][j][3] + by;
            if (res) {
                float2 q0 = *(const float2*)(res + (size_t)r0 * N + cb);
                float2 q1 = *(const float2*)(res + (size_t)r1 * N + cb);
                v0.x += q0.x; v0.y += q0.y; v1.x += q1.x; v1.y += q1.y;
            }
            if (RELU) {
                v0.x = fmaxf(v0.x, 0.f); v0.y = fmaxf(v0.y, 0.f);
                v1.x = fmaxf(v1.x, 0.f); v1.y = fmaxf(v1.y, 0.f);
            }
            *(float2*)(C + (size_t)r0 * N + cb) = v0;
            *(float2*)(C + (size_t)r1 * N + cb) = v1;
        }
    }
}

// ---------------- positional encoding add ----------------
__global__ void add_pe_kernel(float* __restrict__ h) {
    int i = blockIdx.x * blockDim.x + threadIdx.x;
    if (i >= MM * DD) return;
    int d = i % DD;
    int s = (i / DD) % SS;
    float denom = powf(10000.0f, 2.0f * (float)d / (float)DD);
    float ang = (float)s / denom;
    h[i] += (d & 1) ? cosf(ang) : sinf(ang);
}

// ---------------- pack per-layer QKV weights ----------------
__global__ void pack_qkv_kernel(const float* __restrict__ Wq, const float* __restrict__ Wk,
                                const float* __restrict__ Wv,
                                const float* __restrict__ bq, const float* __restrict__ bk,
                                const float* __restrict__ bv) {
    int i = blockIdx.x * blockDim.x + threadIdx.x;
    if (i < DD * (HH * DKK)) {
        int d = i / (HH * DKK);
        int c = i % (HH * DKK);
        int h = c / DKK, kk = c % DKK;
        int src = (h * DD + d) * DKK + kk;
        g_wqkv[d * QKVN + c]                = Wq[src];
        g_wqkv[d * QKVN + (HH * DKK) + c]   = Wk[src];
        g_wqkv[d * QKVN + 2*(HH * DKK) + c] = Wv[src];
    }
    if (i < HH * DKK) {
        g_bqkv[i]              = bq[i];
        g_bqkv[(HH*DKK) + i]   = bk[i];
        g_bqkv[2*(HH*DKK) + i] = bv[i];
    }
}

// ---------------- fused causal attention: 4-way j-parallel online softmax ----------------
// block = 256 threads = 64 queries x 4 slices. grid (S/64, B*H).
__global__ void attn_kernel(const float* __restrict__ qkv, float* __restrict__ ctx) {
    const int qt = blockIdx.x;
    const int bh = blockIdx.y;
    const int b = bh >> 3, h = bh & 7;
    const int tid = threadIdx.x;
    const int ql = tid >> 2, sl = tid & 3;
    const int qidx = qt * 64 + ql;

    __shared__ float Ks[64][DKK];
    __shared__ float Vs[64][DKK];

    const float scale = rsqrtf((float)DKK);
    float q[DKK], o[DKK];
    const float* qrow = qkv + ((size_t)(b * SS + qidx)) * QKVN + h * DKK;
    #pragma unroll
    for (int k = 0; k < DKK; ++k) { q[k] = qrow[k] * scale; o[k] = 0.f; }
    float m = -1e30f, l = 0.f;

    for (int t = 0; t <= qt; ++t) {
        // stage K/V tile
        for (int i = tid; i < 64 * DKK; i += 256) {
            int r = i / DKK, c = i % DKK;
            const float* base = qkv + ((size_t)(b * SS + t * 64 + r)) * QKVN + h * DKK + c;
            Ks[r][c] = base[HH * DKK];
            Vs[r][c] = base[2 * HH * DKK];
        }
        __syncthreads();
        const int jmax = (t == qt) ? ql : 63;
        for (int j = sl; j <= jmax; j += 4) {
            float s0 = 0.f, s1 = 0.f, s2 = 0.f, s3 = 0.f;
            #pragma unroll
            for (int k = 0; k < DKK; k += 4) {
                s0 += q[k]     * Ks[j][k];
                s1 += q[k + 1] * Ks[j][k + 1];
                s2 += q[k + 2] * Ks[j][k + 2];
                s3 += q[k + 3] * Ks[j][k + 3];
            }
            float s = (s0 + s1) + (s2 + s3);
            float mn = fmaxf(m, s);
            float sc = __expf(m - mn);
            float p  = __expf(s - mn);
            l = l * sc + p;
            m = mn;
            #pragma unroll
            for (int k = 0; k < DKK; ++k) o[k] = o[k] * sc + p * Vs[j][k];
        }
        __syncthreads();
    }

    // merge 4 slices of each query (lanes sl=0..3, xor within quad)
    #pragma unroll
    for (int off = 1; off <= 2; off <<= 1) {
        float mo = __shfl_xor_sync(0xffffffffu, m, off);
        float lo = __shfl_xor_sync(0xffffffffu, l, off);
        float mn = fmaxf(m, mo);
        float ss = __expf(m - mn);
        float so = __expf(mo - mn);
        l = l * ss + lo * so;
        #pragma unroll
        for (int k = 0; k < DKK; ++k) {
            float oo = __shfl_xor_sync(0xffffffffu, o[k], off);
            o[k] = o[k] * ss + oo * so;
        }
        m = mn;
    }
    if (sl == 0) {
        float inv = 1.0f / l;
        float* out = ctx + ((size_t)(b * SS + qidx)) * DD + h * DKK;
        #pragma unroll
        for (int k = 0; k < DKK; ++k) out[k] = o[k] * inv;
    }
}

// ---------------- LayerNorm over (S,D) per batch: 2 kernels ----------------
__global__ void ln_partial_kernel(const float* __restrict__ x) {
    const int b = blockIdx.y, g = blockIdx.x;      // 64 chunks of 3584 floats
    const float4* p = (const float4*)(x + (size_t)b * SD + (size_t)g * (SD / 64));
    float s = 0.f, ss = 0.f;
    for (int i = threadIdx.x; i < (SD / 64) / 4; i += 256) {
        float4 v = p[i];
        s  += (v.x + v.y) + (v.z + v.w);
        ss += (v.x * v.x + v.y * v.y) + (v.z * v.z + v.w * v.w);
    }
    __shared__ float rs[256], rss[256];
    rs[threadIdx.x] = s; rss[threadIdx.x] = ss;
    __syncthreads();
    for (int o = 128; o > 0; o >>= 1) {
        if (threadIdx.x < o) { rs[threadIdx.x] += rs[threadIdx.x+o]; rss[threadIdx.x] += rss[threadIdx.x+o]; }
        __syncthreads();
    }
    if (threadIdx.x == 0) g_part[b * 64 + g] = make_float2(rs[0], rss[0]);
}

// normalize; folds the final reduction of the 64 partials into each block
__global__ void ln_norm_kernel(const float* __restrict__ x, const float* __restrict__ w,
                               const float* __restrict__ bw, float* __restrict__ out) {
    const int b = (int)(((size_t)blockIdx.x * 1024) / SD);
    __shared__ float s_mu, s_is;
    if (threadIdx.x < 32) {
        float2 p0 = g_part[b * 64 + threadIdx.x];
        float2 p1 = g_part[b * 64 + threadIdx.x + 32];
        float s = p0.x + p1.x, ss = p0.y + p1.y;
        #pragma unroll
        for (int o = 16; o > 0; o >>= 1) {
            s  += __shfl_down_sync(0xffffffffu, s,  o);
            ss += __shfl_down_sync(0xffffffffu, ss, o);
        }
        if (threadIdx.x == 0) {
            float mu = s / (float)SD;
            float var = ss / (float)SD - mu * mu;
            s_mu = mu;
            s_is = rsqrtf(var + 1e-5f);
        }
    }
    __syncthreads();
    const float mu = s_mu, is = s_is;
    const size_t gi = (size_t)blockIdx.x * 256 + threadIdx.x;   // float4 index
    const size_t sd4 = gi * 4 - (size_t)b * SD;                 // offset within batch
    float4 xv = *(const float4*)(x + (size_t)b * SD + sd4);
    float4 wv = *(const float4*)(w + sd4);
    float4 bv = *(const float4*)(bw + sd4);
    float4 r;
    r.x = (xv.x - mu) * is * wv.x + bv.x;
    r.y = (xv.y - mu) * is * wv.y + bv.y;
    r.z = (xv.z - mu) * is * wv.z + bv.z;
    r.w = (xv.w - mu) * is * wv.w + bv.w;
    *(float4*)(out + (size_t)b * SD + sd4) = r;
}

// ---------------- row softmax over V (in-place on d_out) ----------------
__global__ void softmax_kernel(float* __restrict__ x) {
    const int row = blockIdx.x;
    float4* p = (float4*)(x + (size_t)row * VV);
    __shared__ float red[256];
    float mx = -1e30f;
    for (int i = threadIdx.x; i < VV / 4; i += 256) {
        float4 v = p[i];
        mx = fmaxf(mx, fmaxf(fmaxf(v.x, v.y), fmaxf(v.z, v.w)));
    }
    red[threadIdx.x] = mx; __syncthreads();
    for (int o = 128; o > 0; o >>= 1) {
        if (threadIdx.x < o) red[threadIdx.x] = fmaxf(red[threadIdx.x], red[threadIdx.x + o]);
        __syncthreads();
    }
    mx = red[0]; __syncthreads();
    float sum = 0.f;
    for (int i = threadIdx.x; i < VV / 4; i += 256) {
        float4 v = p[i];
        v.x = __expf(v.x - mx); v.y = __expf(v.y - mx);
        v.z = __expf(v.z - mx); v.w = __expf(v.w - mx);
        p[i] = v;
        sum += (v.x + v.y) + (v.z + v.w);
    }
    red[threadIdx.x] = sum; __syncthreads();
    for (int o = 128; o > 0; o >>= 1) {
        if (threadIdx.x < o) red[threadIdx.x] += red[threadIdx.x + o];
        __syncthreads();
    }
    float inv = 1.0f / red[0];
    for (int i = threadIdx.x; i < VV / 4; i += 256) {
        float4 v = p[i];
        v.x *= inv; v.y *= inv; v.z *= inv; v.w *= inv;
        p[i] = v;
    }
}

// ---------------- host-side orchestration ----------------
static inline void run_gemm(const float* A, const float* B, const float* bias,
                            const float* res, float* C, int M, int N, int K, bool relu) {
    if (N <= 256) {
        dim3 grid((N + 127) / 128, M / 64);
        if (relu) bgemm_kernel<64, true><<<grid, 256>>>(A, B, bias, res, C, M, N, K);
        else      bgemm_kernel<64, false><<<grid, 256>>>(A, B, bias, res, C, M, N, K);
    } else {
        dim3 grid((N + 127) / 128, M / 128);
        if (relu) bgemm_kernel<128, true><<<grid, 256>>>(A, B, bias, res, C, M, N, K);
        else      bgemm_kernel<128, false><<<grid, 256>>>(A, B, bias, res, C, M, N, K);
    }
}

static inline void run_ln(const float* x, const float* w, const float* bw, float* out) {
    dim3 pg(64, BB);
    ln_partial_kernel<<<pg, 256>>>(x);
    ln_norm_kernel<<<(BB * SD) / 1024, 256>>>(x, w, bw, out);
}

extern "C" void kernel_launch(void* const* d_in, const int* in_sizes, int n_in,
                              void* d_out, int out_size) {
    const float* x   = (const float*)d_in[0];
    const float* Wp  = (const float*)d_in[1];
    const float* bp  = (const float*)d_in[2];
    const float* Wq  = (const float*)d_in[3];
    const float* bq  = (const float*)d_in[4];
    const float* Wk  = (const float*)d_in[5];
    const float* bk  = (const float*)d_in[6];
    const float* Wv  = (const float*)d_in[7];
    const float* bv  = (const float*)d_in[8];
    const float* Wo  = (const float*)d_in[9];
    const float* bo  = (const float*)d_in[10];
    const float* W1  = (const float*)d_in[11];
    const float* b1  = (const float*)d_in[12];
    const float* W2  = (const float*)d_in[13];
    const float* b2  = (const float*)d_in[14];
    const float* W3  = (const float*)d_in[15];
    const float* b3  = (const float*)d_in[16];
    const float* lnw = (const float*)d_in[17];
    const float* lnb = (const float*)d_in[18];
    const float* Wf  = (const float*)d_in[19];
    const float* bf  = (const float*)d_in[20];
    float* out = (float*)d_out;

    float *p_h, *p_a, *p_ctx, *p_qkv, *p_f1, *p_f2, *p_wqkv, *p_bqkv;
    cudaGetSymbolAddress((void**)&p_h,    g_h);
    cudaGetSymbolAddress((void**)&p_a,    g_a);
    cudaGetSymbolAddress((void**)&p_ctx,  g_ctx);
    cudaGetSymbolAddress((void**)&p_qkv,  g_qkv);
    cudaGetSymbolAddress((void**)&p_f1,   g_f1);
    cudaGetSymbolAddress((void**)&p_f2,   g_f2);
    cudaGetSymbolAddress((void**)&p_wqkv, g_wqkv);
    cudaGetSymbolAddress((void**)&p_bqkv, g_bqkv);

    // 1) input projection + positional encoding
    run_gemm(x, Wp, bp, nullptr, p_h, MM, DD, DIN, false);
    add_pe_kernel<<<(MM * DD + 255) / 256, 256>>>(p_h);

    // 2) transformer layers
    for (int l = 0; l < LL; ++l) {
        const float* Wq_l = Wq + (size_t)l * HH * DD * DKK;
        const float* Wk_l = Wk + (size_t)l * HH * DD * DKK;
        const float* Wv_l = Wv + (size_t)l * HH * DD * DKK;
        const float* bq_l = bq + (size_t)l * HH * DKK;
        const float* bk_l = bk + (size_t)l * HH * DKK;
        const float* bv_l = bv + (size_t)l * HH * DKK;
        const float* Wo_l = Wo + (size_t)l * DD * DD;
        const float* bo_l = bo + (size_t)l * DD;
        const float* W1_l = W1 + (size_t)l * DD * FFD;
        const float* b1_l = b1 + (size_t)l * FFD;
        const float* W2_l = W2 + (size_t)l * FFD * FFD;
        const float* b2_l = b2 + (size_t)l * FFD;
        const float* W3_l = W3 + (size_t)l * FFD * DD;
        const float* b3_l = b3 + (size_t)l * DD;
        const float* lnw_l = lnw + (size_t)l * SD;
        const float* lnb_l = lnb + (size_t)l * SD;

        pack_qkv_kernel<<<(DD * HH * DKK + 255) / 256, 256>>>(Wq_l, Wk_l, Wv_l, bq_l, bk_l, bv_l);
        run_gemm(p_h, p_wqkv, p_bqkv, nullptr, p_qkv, MM, QKVN, DD, false);
        dim3 ag(SS / 64, BB * HH);
        attn_kernel<<<ag, 256>>>(p_qkv, p_ctx);
        run_gemm(p_ctx, Wo_l, bo_l, p_h, p_a, MM, DD, DD, false);
        run_ln(p_a, lnw_l, lnb_l, p_h);
        run_gemm(p_h,  W1_l, b1_l, nullptr, p_f1, MM, FFD, DD,  true);
        run_gemm(p_f1, W2_l, b2_l, nullptr, p_f2, MM, FFD, FFD, true);
        run_gemm(p_f2, W3_l, b3_l, p_h,     p_a,  MM, DD,  FFD, false);
        run_ln(p_a,   lnw_l, lnb_l, p_ctx);
        run_ln(p_ctx, lnw_l, lnb_l, p_h);
    }

    // 3) vocab projection (into d_out) + softmax in-place
    run_gemm(p_h, Wf, bf, nullptr, out, MM, VV, DD, false);
    softmax_kernel<<<MM, 256>>>(out);
    (void)in_sizes; (void)n_in; (void)out_size;
}